// round 4
// baseline (speedup 1.0000x reference)
#include <cuda_runtime.h>

#define TT   256
#define BB   1024
#define NN   32
#define HH   64
#define RR   8
#define NBLK 128
#define NTHR 256
#define SMEM_FLOATS 44576
#define SMEM_BYTES  (SMEM_FLOATS * 4)

__device__ float gMsumInv[TT];
__device__ float gXloss[NBLK];
__device__ float gYsum[NBLK];
__device__ float gTsum[NBLK];

__device__ __forceinline__ float sigmf(float x) { return 1.0f / (1.0f + __expf(-x)); }
__device__ __forceinline__ float tanhfast(float x) { return 2.0f / (1.0f + __expf(-2.0f * x)) - 1.0f; }

// ---------------------------------------------------------------------------
// K1: per-timestep batch-global mask sum -> 1/(sum+eps)
// ---------------------------------------------------------------------------
__global__ void k_msum(const float* __restrict__ masks) {
    const int t = blockIdx.x;
    const float* p = masks + (size_t)t * NN;
    float s = 0.f;
    for (int i = threadIdx.x; i < BB * NN; i += blockDim.x) {
        int b = i >> 5, n = i & 31;
        s += p[(size_t)b * (TT * NN) + n];
    }
#pragma unroll
    for (int o = 16; o; o >>= 1) s += __shfl_xor_sync(0xffffffffu, s, o);
    __shared__ float red[8];
    if ((threadIdx.x & 31) == 0) red[threadIdx.x >> 5] = s;
    __syncthreads();
    if (threadIdx.x == 0) {
        float tot = 0.f;
#pragma unroll
        for (int i = 0; i < 8; i++) tot += red[i];
        gMsumInv[t] = 1.0f / (tot + 1e-5f);
    }
}

// ---------------------------------------------------------------------------
// K2: persistent recurrence. 128 CTAs x 256 threads, 8 batch rows per CTA.
// Role A: warp rA (=tid>>5) owns batch row rA; lane nA = series index.
// Role B: (jB = tid&63, row-pair rgB = tid>>6) owns LSTM state.
// 4 full barriers per step; role-A internal ordering is warp-local.
// ---------------------------------------------------------------------------
__global__ void __launch_bounds__(NTHR, 1)
k_main(const float* __restrict__ values, const float* __restrict__ masks,
       const float* __restrict__ deltas, const float* __restrict__ labels,
       const float* __restrict__ is_train,
       const float* __restrict__ td_h_W, const float* __restrict__ td_h_b,
       const float* __restrict__ td_x_W, const float* __restrict__ td_x_b,
       const float* __restrict__ hist_W, const float* __restrict__ hist_b,
       const float* __restrict__ feat_W, const float* __restrict__ feat_b,
       const float* __restrict__ wc_W,   const float* __restrict__ wc_b,
       const float* __restrict__ W_ih,   const float* __restrict__ W_hh,
       const float* __restrict__ b_ih,   const float* __restrict__ b_hh,
       const float* __restrict__ out_W,  const float* __restrict__ out_b,
       float* __restrict__ out_pred, float* __restrict__ out_imp)
{
    extern __shared__ float sm[];
    float* sWih   = sm;                 // [64][256]  Wih_t[k][j] = W_ih[j][k]
    float* sWhh   = sWih   + 64 * 256;  // [64][256]
    float* sWth   = sWhh   + 64 * 256;  // [32][64]   td_h_Wt[n][j]
    float* sWhist = sWth   + 2048;      // [64][32]   hist_Wt[j][n]
    float* sWfeat = sWhist + 2048;      // [32][32]   featWt[k][n], diag zeroed
    float* sWwc   = sWfeat + 1024;      // [64][32]   wcWt[k][n]
    float* sBth   = sWwc   + 2048;      // 64
    float* sTdxD  = sBth   + 64;        // 32
    float* sTdxB  = sTdxD  + 32;        // 32
    float* sBhist = sTdxB  + 32;        // 32
    float* sBfeat = sBhist + 32;        // 32
    float* sBwc   = sBfeat + 32;        // 32
    float* sBg    = sBwc   + 32;        // 256 (b_ih + b_hh)
    float* sOutW  = sBg    + 256;       // 64
    float* sdT    = sOutW  + 64;        // [32][8]
    float* smT    = sdT    + 256;       // [32][8]
    float* shT    = smT    + 256;       // [64][8]
    float* sxcT   = shT    + 512;       // [32][8]
    float* sgxT   = sxcT   + 256;       // [32][8]
    float* sinpT  = sgxT   + 256;       // [64][8]  (c_c ; m)
    float* sgT    = sinpT  + 512;       // [8][256] gates

    const int tid = threadIdx.x;
    const int b0  = blockIdx.x * RR;

    // ---- stage weights (transposed; coalesced global reads) ----
    for (int i = tid; i < 64 * 256; i += NTHR) { int j = i >> 6, k = i & 63; sWih[k * 256 + j] = W_ih[i]; }
    for (int i = tid; i < 64 * 256; i += NTHR) { int j = i >> 6, k = i & 63; sWhh[k * 256 + j] = W_hh[i]; }
    for (int i = tid; i < 2048; i += NTHR)     { int j = i >> 5, n = i & 31; sWth[n * 64 + j] = td_h_W[i]; }
    for (int i = tid; i < 2048; i += NTHR)     { int n = i >> 6, j = i & 63; sWhist[j * 32 + n] = hist_W[i]; }
    for (int i = tid; i < 1024; i += NTHR)     { int n = i >> 5, k = i & 31; sWfeat[k * 32 + n] = (n == k) ? 0.0f : feat_W[i]; }
    for (int i = tid; i < 2048; i += NTHR)     { int n = i >> 6, k = i & 63; sWwc[k * 32 + n] = wc_W[i]; }
    if (tid < 64) { sBth[tid] = td_h_b[tid]; sOutW[tid] = out_W[tid]; }
    if (tid < 32) {
        sTdxD[tid] = td_x_W[tid * NN + tid]; sTdxB[tid] = td_x_b[tid];
        sBhist[tid] = hist_b[tid]; sBfeat[tid] = feat_b[tid]; sBwc[tid] = wc_b[tid];
    }
    sBg[tid] = b_ih[tid] + b_hh[tid];
    __syncthreads();

    const int nA = tid & 31, rA = tid >> 5;   // role A: (series n, row r) — row == warp
    const int jB = tid & 63, rgB = tid >> 6;  // role B: (hidden j, row-pair)

    float h0 = 0.f, h1 = 0.f, c0 = 0.f, c1 = 0.f;  // LSTM state for rows 2rgB, 2rgB+1 at index jB
    float lossAcc = 0.f;

    const size_t rowBase = (size_t)(b0 + rA) * TT * NN + nA;

    // prefetched t=0 inputs
    float x = values[rowBase];
    float m = masks[rowBase];
    float d = deltas[rowBase];
    float inv_ms = gMsumInv[0];

    for (int t = 0; t < TT; t++) {
        const size_t off = rowBase + (size_t)t * NN;
        sdT[nA * 8 + rA] = d;
        smT[nA * 8 + rA] = m;
        __syncthreads();  // S1: sdT/smT -> role B (cross-warp)

        // ---- gamma_h + hidden decay (thread = (jB, rows 2rgB,2rgB+1)) ----
        {
            float a0 = sBth[jB], a1 = a0;
            const float*  wp = sWth + jB;
            const float2* dp = (const float2*)sdT + rgB;
#pragma unroll 8
            for (int n = 0; n < 32; n++) {
                float  w  = wp[n * 64];
                float2 dd = dp[n * 4];
                a0 = fmaf(w, dd.x, a0);
                a1 = fmaf(w, dd.y, a1);
            }
            h0 *= __expf(-fmaxf(a0, 0.f));
            h1 *= __expf(-fmaxf(a1, 0.f));
            shT[jB * 8 + 2 * rgB]     = h0;
            shT[jB * 8 + 2 * rgB + 1] = h1;
        }
        __syncthreads();  // S2: shT -> role A (cross-warp)

        // ---- role A fused segment: x_h / x_c / gamma_x, then z_h / alpha /
        //      c_h / c_c / loss. All sxcT/sgxT/smT traffic at row rA stays
        //      inside warp rA, so only __syncwarp() is needed mid-segment. ----
        {
            float acc = sBhist[nA];
#pragma unroll 8
            for (int j = 0; j < 64; j++) acc = fmaf(sWhist[j * 32 + nA], shT[j * 8 + rA], acc);
            const float x_h = acc;
            float xc = fmaf(m, x - x_h, x_h);           // m*x + (1-m)*x_h
            sxcT[nA * 8 + rA] = xc;
            float gx = __expf(-fmaxf(fmaf(d, sTdxD[nA], sTdxB[nA]), 0.f));
            sgxT[nA * 8 + rA] = gx;
            const float e1 = fabsf(x - x_h);
            __syncwarp();  // intra-warp ordering for sxcT/sgxT

            float z = sBfeat[nA];
#pragma unroll 8
            for (int k = 0; k < 32; k++) z = fmaf(sWfeat[k * 32 + nA], sxcT[k * 8 + rA], z);
            float al = sBwc[nA];
#pragma unroll 8
            for (int k = 0; k < 32; k++) al = fmaf(sWwc[k * 32 + nA], sgxT[k * 8 + rA], al);
#pragma unroll 8
            for (int k = 0; k < 32; k++) al = fmaf(sWwc[(k + 32) * 32 + nA], smT[k * 8 + rA], al);
            float ch = fmaf(al, z - x_h, x_h);           // alpha*z_h + (1-alpha)*x_h
            float cc = fmaf(m, x - ch, ch);              // m*x + (1-m)*c_h
            lossAcc = fmaf((e1 + fabsf(x - z) + fabsf(x - ch)) * m, inv_ms, lossAcc);
            out_imp[off] = cc;
            sinpT[nA * 8 + rA]        = cc;
            sinpT[(nA + 32) * 8 + rA] = m;
        }
        __syncthreads();  // S4: sinpT -> all (cross-warp)

        // ---- prefetch t+1 inputs: LDG latency hides behind the gates GEMM ----
        {
            const int tn = (t + 1 < TT) ? (t + 1) : t;   // clamp: tail value unused
            const size_t offn = rowBase + (size_t)tn * NN;
            x      = values[offn];
            m      = masks[offn];
            d      = deltas[offn];
            inv_ms = gMsumInv[tn];
        }

        // ---- gates GEMM: thread = gate column, 8-row register block ----
        {
            float a[8];
            const float bg = sBg[tid];
#pragma unroll
            for (int r = 0; r < 8; r++) a[r] = bg;
#pragma unroll 8
            for (int k = 0; k < 64; k++) {
                float  w = sWih[k * 256 + tid];
                float4 p = *(const float4*)(sinpT + k * 8);
                float4 q = *(const float4*)(sinpT + k * 8 + 4);
                a[0] = fmaf(w, p.x, a[0]); a[1] = fmaf(w, p.y, a[1]);
                a[2] = fmaf(w, p.z, a[2]); a[3] = fmaf(w, p.w, a[3]);
                a[4] = fmaf(w, q.x, a[4]); a[5] = fmaf(w, q.y, a[5]);
                a[6] = fmaf(w, q.z, a[6]); a[7] = fmaf(w, q.w, a[7]);
            }
#pragma unroll 8
            for (int k = 0; k < 64; k++) {
                float  w = sWhh[k * 256 + tid];
                float4 p = *(const float4*)(shT + k * 8);
                float4 q = *(const float4*)(shT + k * 8 + 4);
                a[0] = fmaf(w, p.x, a[0]); a[1] = fmaf(w, p.y, a[1]);
                a[2] = fmaf(w, p.z, a[2]); a[3] = fmaf(w, p.w, a[3]);
                a[4] = fmaf(w, q.x, a[4]); a[5] = fmaf(w, q.y, a[5]);
                a[6] = fmaf(w, q.z, a[6]); a[7] = fmaf(w, q.w, a[7]);
            }
#pragma unroll
            for (int r = 0; r < 8; r++) sgT[r * 256 + tid] = a[r];
        }
        __syncthreads();  // S5: sgT -> role B (cross-warp)

        // ---- LSTM cell update (thread = (jB, rows 2rgB, 2rgB+1)) ----
        {
            const float* g0 = sgT + (2 * rgB) * 256;
            float gi = g0[jB], gf = g0[64 + jB], gg = g0[128 + jB], go = g0[192 + jB];
            c0 = sigmf(gf) * c0 + sigmf(gi) * tanhfast(gg);
            h0 = sigmf(go) * tanhfast(c0);
            const float* g1 = sgT + (2 * rgB + 1) * 256;
            gi = g1[jB]; gf = g1[64 + jB]; gg = g1[128 + jB]; go = g1[192 + jB];
            c1 = sigmf(gf) * c1 + sigmf(gi) * tanhfast(gg);
            h1 = sigmf(go) * tanhfast(c1);
        }
        // no trailing sync needed: next S1 orders sdT/smT rewrite; sgT rewrite is
        // behind S4 of the next iteration.
    }

    // ---- output head ----
    shT[jB * 8 + 2 * rgB]     = h0;
    shT[jB * 8 + 2 * rgB + 1] = h1;
    __syncthreads();

    const int w = tid >> 5, lane = tid & 31;
    float y = sOutW[lane] * shT[lane * 8 + w] + sOutW[lane + 32] * shT[(lane + 32) * 8 + w];
#pragma unroll
    for (int o = 16; o; o >>= 1) y += __shfl_xor_sync(0xffffffffu, y, o);
    float yLoc = 0.f, tLoc = 0.f;
    if (lane == 0) {
        y += out_b[0];
        out_pred[b0 + w] = sigmf(y);
        float lab = labels[b0 + w];
        float itr = is_train[b0 + w];
        float mv  = fmaxf(-y, 0.f);
        float bce = y - y * lab + mv + __logf(__expf(-mv) + __expf(-y - mv));
        yLoc = bce * itr;
        tLoc = itr;
    }

#pragma unroll
    for (int o = 16; o; o >>= 1) lossAcc += __shfl_xor_sync(0xffffffffu, lossAcc, o);
    __syncthreads();
    if (lane == 0) { sdT[w] = lossAcc; smT[w] = yLoc; smT[8 + w] = tLoc; }
    __syncthreads();
    if (tid == 0) {
        float xl = 0.f, ys = 0.f, ts = 0.f;
#pragma unroll
        for (int i = 0; i < 8; i++) { xl += sdT[i]; ys += smT[i]; ts += smT[8 + i]; }
        gXloss[blockIdx.x] = xl;
        gYsum[blockIdx.x]  = ys;
        gTsum[blockIdx.x]  = ts;
    }
}

// ---------------------------------------------------------------------------
// K3: deterministic final combine
// ---------------------------------------------------------------------------
__global__ void k_final(float* __restrict__ out) {
    float xl = 0.f, ys = 0.f, ts = 0.f;
    for (int i = 0; i < NBLK; i++) { xl += gXloss[i]; ys += gYsum[i]; ts += gTsum[i]; }
    out[0] = xl / (float)TT + 0.1f * (ys / (ts + 1e-5f));
}

extern "C" void kernel_launch(void* const* d_in, const int* in_sizes, int n_in,
                              void* d_out, int out_size) {
    const float* values   = (const float*)d_in[0];
    const float* masks    = (const float*)d_in[1];
    const float* deltas   = (const float*)d_in[2];
    // d_in[3] evals, d_in[4] eval_masks: unused by the forward outputs
    const float* labels   = (const float*)d_in[5];
    const float* is_train = (const float*)d_in[6];
    const float* td_h_W   = (const float*)d_in[7];
    const float* td_h_b   = (const float*)d_in[8];
    const float* td_x_W   = (const float*)d_in[9];
    const float* td_x_b   = (const float*)d_in[10];
    const float* hist_W   = (const float*)d_in[11];
    const float* hist_b   = (const float*)d_in[12];
    const float* feat_W   = (const float*)d_in[13];
    const float* feat_b   = (const float*)d_in[14];
    const float* wc_W     = (const float*)d_in[15];
    const float* wc_b     = (const float*)d_in[16];
    const float* W_ih     = (const float*)d_in[17];
    const float* W_hh     = (const float*)d_in[18];
    const float* b_ih     = (const float*)d_in[19];
    const float* b_hh     = (const float*)d_in[20];
    const float* out_W    = (const float*)d_in[21];
    const float* out_b    = (const float*)d_in[22];
    float* out = (float*)d_out;

    cudaFuncSetAttribute(k_main, cudaFuncAttributeMaxDynamicSharedMemorySize, SMEM_BYTES);

    // out layout: [loss(1) | predictions(B) | imputations(B*T*N)]
    k_msum<<<TT, 256>>>(masks);
    k_main<<<NBLK, NTHR, SMEM_BYTES>>>(values, masks, deltas, labels, is_train,
                                       td_h_W, td_h_b, td_x_W, td_x_b,
                                       hist_W, hist_b, feat_W, feat_b,
                                       wc_W, wc_b, W_ih, W_hh, b_ih, b_hh,
                                       out_W, out_b,
                                       out + 1, out + 1 + BB);
    k_final<<<1, 1>>>(out);
}

// round 8
// speedup vs baseline: 1.0185x; 1.0185x over previous
#include <cuda_runtime.h>

#define TT   256
#define BB   1024
#define NN   32
#define HH   64
#define RR   8
#define NBLK 128
#define NTHR 256
#define SMEM_FLOATS 44576
#define SMEM_BYTES  (SMEM_FLOATS * 4)

__device__ float gMsumInv[TT];
__device__ float gXloss[NBLK];
__device__ float gYsum[NBLK];
__device__ float gTsum[NBLK];

__device__ __forceinline__ float sigmf(float x) { return 1.0f / (1.0f + __expf(-x)); }
__device__ __forceinline__ float tanhfast(float x) { return 2.0f / (1.0f + __expf(-2.0f * x)) - 1.0f; }

// packed fp32x2 helpers (sm_100+ PTX; ptxas never auto-fuses these)
#define PACK2(dst, lo, hi) \
    asm("mov.b64 %0, {%1, %2};" : "=l"(dst) : "r"(lo), "r"(hi))
#define UNPACK2(lo, hi, src) \
    asm("mov.b64 {%0, %1}, %2;" : "=r"(lo), "=r"(hi) : "l"(src))
#define FMA2(d, a, b, c) \
    asm("fma.rn.f32x2 %0, %1, %2, %3;" : "=l"(d) : "l"(a), "l"(b), "l"(c))

// ---------------------------------------------------------------------------
// K1: per-timestep batch-global mask sum -> 1/(sum+eps)
// ---------------------------------------------------------------------------
__global__ void k_msum(const float* __restrict__ masks) {
    const int t = blockIdx.x;
    const float* p = masks + (size_t)t * NN;
    float s = 0.f;
    for (int i = threadIdx.x; i < BB * NN; i += blockDim.x) {
        int b = i >> 5, n = i & 31;
        s += p[(size_t)b * (TT * NN) + n];
    }
#pragma unroll
    for (int o = 16; o; o >>= 1) s += __shfl_xor_sync(0xffffffffu, s, o);
    __shared__ float red[8];
    if ((threadIdx.x & 31) == 0) red[threadIdx.x >> 5] = s;
    __syncthreads();
    if (threadIdx.x == 0) {
        float tot = 0.f;
#pragma unroll
        for (int i = 0; i < 8; i++) tot += red[i];
        gMsumInv[t] = 1.0f / (tot + 1e-5f);
    }
}

// ---------------------------------------------------------------------------
// K2: persistent recurrence. 128 CTAs x 256 threads, 8 batch rows per CTA.
// Role A: warp rA (=tid>>5) owns batch row rA; lane nA = series index.
// Role B: (jB = tid&63, row-pair rgB = tid>>6) owns LSTM state.
// Gates GEMM + gamma_h use packed fma.rn.f32x2 (2 FMA / issue).
// ---------------------------------------------------------------------------
__global__ void __launch_bounds__(NTHR, 1)
k_main(const float* __restrict__ values, const float* __restrict__ masks,
       const float* __restrict__ deltas, const float* __restrict__ labels,
       const float* __restrict__ is_train,
       const float* __restrict__ td_h_W, const float* __restrict__ td_h_b,
       const float* __restrict__ td_x_W, const float* __restrict__ td_x_b,
       const float* __restrict__ hist_W, const float* __restrict__ hist_b,
       const float* __restrict__ feat_W, const float* __restrict__ feat_b,
       const float* __restrict__ wc_W,   const float* __restrict__ wc_b,
       const float* __restrict__ W_ih,   const float* __restrict__ W_hh,
       const float* __restrict__ b_ih,   const float* __restrict__ b_hh,
       const float* __restrict__ out_W,  const float* __restrict__ out_b,
       float* __restrict__ out_pred, float* __restrict__ out_imp)
{
    extern __shared__ float sm[];
    float* sWih   = sm;                 // [64][256]  Wih_t[k][j] = W_ih[j][k]
    float* sWhh   = sWih   + 64 * 256;  // [64][256]
    float* sWth   = sWhh   + 64 * 256;  // [32][64]   td_h_Wt[n][j]
    float* sWhist = sWth   + 2048;      // [64][32]   hist_Wt[j][n]
    float* sWfeat = sWhist + 2048;      // [32][32]   featWt[k][n], diag zeroed
    float* sWwc   = sWfeat + 1024;      // [64][32]   wcWt[k][n]
    float* sBth   = sWwc   + 2048;      // 64
    float* sTdxD  = sBth   + 64;        // 32
    float* sTdxB  = sTdxD  + 32;        // 32
    float* sBhist = sTdxB  + 32;        // 32
    float* sBfeat = sBhist + 32;        // 32
    float* sBwc   = sBfeat + 32;        // 32
    float* sBg    = sBwc   + 32;        // 256 (b_ih + b_hh)
    float* sOutW  = sBg    + 256;       // 64
    float* sdT    = sOutW  + 64;        // [32][8]
    float* smT    = sdT    + 256;       // [32][8]
    float* shT    = smT    + 256;       // [64][8]
    float* sxcT   = shT    + 512;       // [32][8]
    float* sgxT   = sxcT   + 256;       // [32][8]
    float* sinpT  = sgxT   + 256;       // [64][8]  (c_c ; m)
    float* sgT    = sinpT  + 512;       // [8][256] gates

    const int tid = threadIdx.x;
    const int b0  = blockIdx.x * RR;

    // ---- stage weights (transposed; coalesced global reads) ----
    for (int i = tid; i < 64 * 256; i += NTHR) { int j = i >> 6, k = i & 63; sWih[k * 256 + j] = W_ih[i]; }
    for (int i = tid; i < 64 * 256; i += NTHR) { int j = i >> 6, k = i & 63; sWhh[k * 256 + j] = W_hh[i]; }
    for (int i = tid; i < 2048; i += NTHR)     { int j = i >> 5, n = i & 31; sWth[n * 64 + j] = td_h_W[i]; }
    for (int i = tid; i < 2048; i += NTHR)     { int n = i >> 6, j = i & 63; sWhist[j * 32 + n] = hist_W[i]; }
    for (int i = tid; i < 1024; i += NTHR)     { int n = i >> 5, k = i & 31; sWfeat[k * 32 + n] = (n == k) ? 0.0f : feat_W[i]; }
    for (int i = tid; i < 2048; i += NTHR)     { int n = i >> 6, k = i & 63; sWwc[k * 32 + n] = wc_W[i]; }
    if (tid < 64) { sBth[tid] = td_h_b[tid]; sOutW[tid] = out_W[tid]; }
    if (tid < 32) {
        sTdxD[tid] = td_x_W[tid * NN + tid]; sTdxB[tid] = td_x_b[tid];
        sBhist[tid] = hist_b[tid]; sBfeat[tid] = feat_b[tid]; sBwc[tid] = wc_b[tid];
    }
    sBg[tid] = b_ih[tid] + b_hh[tid];
    __syncthreads();

    const int nA = tid & 31, rA = tid >> 5;   // role A: (series n, row r) — row == warp
    const int jB = tid & 63, rgB = tid >> 6;  // role B: (hidden j, row-pair)

    float h0 = 0.f, h1 = 0.f, c0 = 0.f, c1 = 0.f;  // LSTM state for rows 2rgB, 2rgB+1 at index jB
    float lossAcc = 0.f;

    const size_t rowBase = (size_t)(b0 + rA) * TT * NN + nA;

    // prefetched t=0 inputs
    float x = values[rowBase];
    float m = masks[rowBase];
    float d = deltas[rowBase];
    float inv_ms = gMsumInv[0];

    for (int t = 0; t < TT; t++) {
        const size_t off = rowBase + (size_t)t * NN;
        sdT[nA * 8 + rA] = d;
        smT[nA * 8 + rA] = m;
        __syncthreads();  // S1: sdT/smT -> role B (cross-warp)

        // ---- gamma_h + hidden decay (packed rows 2rgB,2rgB+1) ----
        {
            const float bth = sBth[jB];
            unsigned long long acc; PACK2(acc, __float_as_uint(bth), __float_as_uint(bth));
            const float* wp = sWth + jB;
            const unsigned long long* dp =
                (const unsigned long long*)(sdT + 2 * rgB);
#pragma unroll 8
            for (int n = 0; n < 32; n++) {
                unsigned int wu = __float_as_uint(wp[n * 64]);
                unsigned long long wd; PACK2(wd, wu, wu);
                FMA2(acc, wd, dp[n * 4], acc);
            }
            unsigned int u0, u1; UNPACK2(u0, u1, acc);
            h0 *= __expf(-fmaxf(__uint_as_float(u0), 0.f));
            h1 *= __expf(-fmaxf(__uint_as_float(u1), 0.f));
            shT[jB * 8 + 2 * rgB]     = h0;
            shT[jB * 8 + 2 * rgB + 1] = h1;
        }
        __syncthreads();  // S2: shT -> role A (cross-warp)

        // ---- role A fused segment (warp-local ordering only) ----
        {
            float acc = sBhist[nA];
#pragma unroll 8
            for (int j = 0; j < 64; j++) acc = fmaf(sWhist[j * 32 + nA], shT[j * 8 + rA], acc);
            const float x_h = acc;
            float xc = fmaf(m, x - x_h, x_h);           // m*x + (1-m)*x_h
            sxcT[nA * 8 + rA] = xc;
            float gx = __expf(-fmaxf(fmaf(d, sTdxD[nA], sTdxB[nA]), 0.f));
            sgxT[nA * 8 + rA] = gx;
            const float e1 = fabsf(x - x_h);
            __syncwarp();  // intra-warp ordering for sxcT/sgxT

            float z = sBfeat[nA];
#pragma unroll 8
            for (int k = 0; k < 32; k++) z = fmaf(sWfeat[k * 32 + nA], sxcT[k * 8 + rA], z);
            float al = sBwc[nA];
#pragma unroll 8
            for (int k = 0; k < 32; k++) al = fmaf(sWwc[k * 32 + nA], sgxT[k * 8 + rA], al);
#pragma unroll 8
            for (int k = 0; k < 32; k++) al = fmaf(sWwc[(k + 32) * 32 + nA], smT[k * 8 + rA], al);
            float ch = fmaf(al, z - x_h, x_h);           // alpha*z_h + (1-alpha)*x_h
            float cc = fmaf(m, x - ch, ch);              // m*x + (1-m)*c_h
            lossAcc = fmaf((e1 + fabsf(x - z) + fabsf(x - ch)) * m, inv_ms, lossAcc);
            out_imp[off] = cc;
            sinpT[nA * 8 + rA]        = cc;
            sinpT[(nA + 32) * 8 + rA] = m;
        }
        __syncthreads();  // S4: sinpT -> all (cross-warp)

        // ---- prefetch t+1 inputs: LDG latency hides behind the gates GEMM ----
        {
            const int tn = (t + 1 < TT) ? (t + 1) : t;   // clamp: tail value unused
            const size_t offn = rowBase + (size_t)tn * NN;
            x      = values[offn];
            m      = masks[offn];
            d      = deltas[offn];
            inv_ms = gMsumInv[tn];
        }

        // ---- gates GEMM: thread = gate column, 8 rows as 4 packed f32x2 accs ----
        {
            unsigned long long a01, a23, a45, a67;
            {
                unsigned int bg = __float_as_uint(sBg[tid]);
                PACK2(a01, bg, bg); PACK2(a23, bg, bg);
                PACK2(a45, bg, bg); PACK2(a67, bg, bg);
            }
#pragma unroll 8
            for (int k = 0; k < 64; k++) {
                unsigned int wu = __float_as_uint(sWih[k * 256 + tid]);
                unsigned long long wd; PACK2(wd, wu, wu);
                ulonglong2 p = *(const ulonglong2*)(sinpT + k * 8);
                ulonglong2 q = *(const ulonglong2*)(sinpT + k * 8 + 4);
                FMA2(a01, wd, p.x, a01); FMA2(a23, wd, p.y, a23);
                FMA2(a45, wd, q.x, a45); FMA2(a67, wd, q.y, a67);
            }
#pragma unroll 8
            for (int k = 0; k < 64; k++) {
                unsigned int wu = __float_as_uint(sWhh[k * 256 + tid]);
                unsigned long long wd; PACK2(wd, wu, wu);
                ulonglong2 p = *(const ulonglong2*)(shT + k * 8);
                ulonglong2 q = *(const ulonglong2*)(shT + k * 8 + 4);
                FMA2(a01, wd, p.x, a01); FMA2(a23, wd, p.y, a23);
                FMA2(a45, wd, q.x, a45); FMA2(a67, wd, q.y, a67);
            }
            unsigned int u0, u1;
            UNPACK2(u0, u1, a01);
            sgT[0 * 256 + tid] = __uint_as_float(u0); sgT[1 * 256 + tid] = __uint_as_float(u1);
            UNPACK2(u0, u1, a23);
            sgT[2 * 256 + tid] = __uint_as_float(u0); sgT[3 * 256 + tid] = __uint_as_float(u1);
            UNPACK2(u0, u1, a45);
            sgT[4 * 256 + tid] = __uint_as_float(u0); sgT[5 * 256 + tid] = __uint_as_float(u1);
            UNPACK2(u0, u1, a67);
            sgT[6 * 256 + tid] = __uint_as_float(u0); sgT[7 * 256 + tid] = __uint_as_float(u1);
        }
        __syncthreads();  // S5: sgT -> role B (cross-warp)

        // ---- LSTM cell update (thread = (jB, rows 2rgB, 2rgB+1)) ----
        {
            const float* g0 = sgT + (2 * rgB) * 256;
            float gi = g0[jB], gf = g0[64 + jB], gg = g0[128 + jB], go = g0[192 + jB];
            c0 = sigmf(gf) * c0 + sigmf(gi) * tanhfast(gg);
            h0 = sigmf(go) * tanhfast(c0);
            const float* g1 = sgT + (2 * rgB + 1) * 256;
            gi = g1[jB]; gf = g1[64 + jB]; gg = g1[128 + jB]; go = g1[192 + jB];
            c1 = sigmf(gf) * c1 + sigmf(gi) * tanhfast(gg);
            h1 = sigmf(go) * tanhfast(c1);
        }
        // no trailing sync needed: next S1 orders sdT/smT rewrite; sgT rewrite is
        // behind S4 of the next iteration.
    }

    // ---- output head ----
    shT[jB * 8 + 2 * rgB]     = h0;
    shT[jB * 8 + 2 * rgB + 1] = h1;
    __syncthreads();

    const int w = tid >> 5, lane = tid & 31;
    float y = sOutW[lane] * shT[lane * 8 + w] + sOutW[lane + 32] * shT[(lane + 32) * 8 + w];
#pragma unroll
    for (int o = 16; o; o >>= 1) y += __shfl_xor_sync(0xffffffffu, y, o);
    float yLoc = 0.f, tLoc = 0.f;
    if (lane == 0) {
        y += out_b[0];
        out_pred[b0 + w] = sigmf(y);
        float lab = labels[b0 + w];
        float itr = is_train[b0 + w];
        float mv  = fmaxf(-y, 0.f);
        float bce = y - y * lab + mv + __logf(__expf(-mv) + __expf(-y - mv));
        yLoc = bce * itr;
        tLoc = itr;
    }

#pragma unroll
    for (int o = 16; o; o >>= 1) lossAcc += __shfl_xor_sync(0xffffffffu, lossAcc, o);
    __syncthreads();
    if (lane == 0) { sdT[w] = lossAcc; smT[w] = yLoc; smT[8 + w] = tLoc; }
    __syncthreads();
    if (tid == 0) {
        float xl = 0.f, ys = 0.f, ts = 0.f;
#pragma unroll
        for (int i = 0; i < 8; i++) { xl += sdT[i]; ys += smT[i]; ts += smT[8 + i]; }
        gXloss[blockIdx.x] = xl;
        gYsum[blockIdx.x]  = ys;
        gTsum[blockIdx.x]  = ts;
    }
}

// ---------------------------------------------------------------------------
// K3: deterministic final combine
// ---------------------------------------------------------------------------
__global__ void k_final(float* __restrict__ out) {
    float xl = 0.f, ys = 0.f, ts = 0.f;
    for (int i = 0; i < NBLK; i++) { xl += gXloss[i]; ys += gYsum[i]; ts += gTsum[i]; }
    out[0] = xl / (float)TT + 0.1f * (ys / (ts + 1e-5f));
}

extern "C" void kernel_launch(void* const* d_in, const int* in_sizes, int n_in,
                              void* d_out, int out_size) {
    const float* values   = (const float*)d_in[0];
    const float* masks    = (const float*)d_in[1];
    const float* deltas   = (const float*)d_in[2];
    // d_in[3] evals, d_in[4] eval_masks: unused by the forward outputs
    const float* labels   = (const float*)d_in[5];
    const float* is_train = (const float*)d_in[6];
    const float* td_h_W   = (const float*)d_in[7];
    const float* td_h_b   = (const float*)d_in[8];
    const float* td_x_W   = (const float*)d_in[9];
    const float* td_x_b   = (const float*)d_in[10];
    const float* hist_W   = (const float*)d_in[11];
    const float* hist_b   = (const float*)d_in[12];
    const float* feat_W   = (const float*)d_in[13];
    const float* feat_b   = (const float*)d_in[14];
    const float* wc_W     = (const float*)d_in[15];
    const float* wc_b     = (const float*)d_in[16];
    const float* W_ih     = (const float*)d_in[17];
    const float* W_hh     = (const float*)d_in[18];
    const float* b_ih     = (const float*)d_in[19];
    const float* b_hh     = (const float*)d_in[20];
    const float* out_W    = (const float*)d_in[21];
    const float* out_b    = (const float*)d_in[22];
    float* out = (float*)d_out;

    cudaFuncSetAttribute(k_main, cudaFuncAttributeMaxDynamicSharedMemorySize, SMEM_BYTES);

    // out layout: [loss(1) | predictions(B) | imputations(B*T*N)]
    k_msum<<<TT, 256>>>(masks);
    k_main<<<NBLK, NTHR, SMEM_BYTES>>>(values, masks, deltas, labels, is_train,
                                       td_h_W, td_h_b, td_x_W, td_x_b,
                                       hist_W, hist_b, feat_W, feat_b,
                                       wc_W, wc_b, W_ih, W_hh, b_ih, b_hh,
                                       out_W, out_b,
                                       out + 1, out + 1 + BB);
    k_final<<<1, 1>>>(out);
}

// round 14
// speedup vs baseline: 1.1586x; 1.1376x over previous
#include <cuda_runtime.h>

#define TT   256
#define BB   1024
#define NN   32
#define HH   64
#define RR   8
#define NBLK 128
#define NTHR 128
#define SMEM_FLOATS 44608
#define SMEM_BYTES  (SMEM_FLOATS * 4)

typedef unsigned long long u64;

__device__ float gMsumInv[TT];
__device__ float gXloss[NBLK];
__device__ float gYsum[NBLK];
__device__ float gTsum[NBLK];

__device__ __forceinline__ float sigmf(float x) { return 1.0f / (1.0f + __expf(-x)); }
__device__ __forceinline__ float tanhfast(float x) { return 2.0f / (1.0f + __expf(-2.0f * x)) - 1.0f; }

#define PACK2(dst, lo, hi) \
    asm("mov.b64 %0, {%1, %2};" : "=l"(dst) : "r"(lo), "r"(hi))
#define UNPACK2(lo, hi, src) \
    asm("mov.b64 {%0, %1}, %2;" : "=r"(lo), "=r"(hi) : "l"(src))
#define FMA2(d, a, b, c) \
    asm("fma.rn.f32x2 %0, %1, %2, %3;" : "=l"(d) : "l"(a), "l"(b), "l"(c))
#define ADD2(d, a, b) \
    asm("add.rn.f32x2 %0, %1, %2;" : "=l"(d) : "l"(a), "l"(b))

__device__ __forceinline__ u64 dupf(float v) {
    u64 r; unsigned int u = __float_as_uint(v); PACK2(r, u, u); return r;
}
__device__ __forceinline__ float lo_f(u64 v) {
    unsigned int a, b; UNPACK2(a, b, v); return __uint_as_float(a);
}
__device__ __forceinline__ float hi_f(u64 v) {
    unsigned int a, b; UNPACK2(a, b, v); return __uint_as_float(b);
}

// ---------------------------------------------------------------------------
// K1: per-timestep batch-global mask sum -> 1/(sum+eps)
// ---------------------------------------------------------------------------
__global__ void k_msum(const float* __restrict__ masks) {
    const int t = blockIdx.x;
    const float* p = masks + (size_t)t * NN;
    float s = 0.f;
    for (int i = threadIdx.x; i < BB * NN; i += blockDim.x) {
        int b = i >> 5, n = i & 31;
        s += p[(size_t)b * (TT * NN) + n];
    }
#pragma unroll
    for (int o = 16; o; o >>= 1) s += __shfl_xor_sync(0xffffffffu, s, o);
    __shared__ float red[8];
    if ((threadIdx.x & 31) == 0) red[threadIdx.x >> 5] = s;
    __syncthreads();
    if (threadIdx.x == 0) {
        float tot = 0.f;
#pragma unroll
        for (int i = 0; i < 8; i++) tot += red[i];
        gMsumInv[t] = 1.0f / (tot + 1e-5f);
    }
}

// ---------------------------------------------------------------------------
// K2: persistent recurrence. 128 CTAs x 128 threads (4 warps), each warp owns
// TWO batch rows -> every weight LDS is reused for 2 rows (halves smem
// traffic to the FMA-pipe floor). Everything warp-local: only __syncwarp()
// in the timestep loop. fma.rn.f32x2 throughout.
// ---------------------------------------------------------------------------
__global__ void __launch_bounds__(NTHR, 1)
k_main(const float* __restrict__ values, const float* __restrict__ masks,
       const float* __restrict__ deltas, const float* __restrict__ labels,
       const float* __restrict__ is_train,
       const float* __restrict__ td_h_W, const float* __restrict__ td_h_b,
       const float* __restrict__ td_x_W, const float* __restrict__ td_x_b,
       const float* __restrict__ hist_W, const float* __restrict__ hist_b,
       const float* __restrict__ feat_W, const float* __restrict__ feat_b,
       const float* __restrict__ wc_W,   const float* __restrict__ wc_b,
       const float* __restrict__ W_ih,   const float* __restrict__ W_hh,
       const float* __restrict__ b_ih,   const float* __restrict__ b_hh,
       const float* __restrict__ out_W,  const float* __restrict__ out_b,
       float* __restrict__ out_pred, float* __restrict__ out_imp)
{
    extern __shared__ float sm[];
    float* sWih2  = sm;              // [64 k][4 gate][32 lane] x2 : cols (2l, 2l+1)
    float* sWhh2  = sWih2  + 16384;  // same layout
    float* sWth2  = sWhh2  + 16384;  // [32 n][32 lane] x2 : rows (2l, 2l+1)
    float* sWhi2  = sWth2  + 2048;   // [32 jp][32 n] x2 : hist pairs over j
    float* sWfe2  = sWhi2  + 2048;   // [16 kp][32 n] x2 : feat (diag zero), pairs over k
    float* sWwc2  = sWfe2  + 1024;   // [32 kp][32 n] x2 : wc pairs over k
    float* sBth   = sWwc2  + 2048;   // 64
    float* sBg    = sBth   + 64;     // 256
    float* sOutW  = sBg    + 256;    // 64
    float* sTdxD  = sOutW  + 64;     // 32
    float* sTdxB  = sTdxD  + 32;     // 32
    float* sBhist = sTdxB  + 32;     // 32
    float* sBfeat = sBhist + 32;     // 32
    float* sBwc   = sBfeat + 32;     // 32
    float* sRed   = sBwc   + 32;     // 32
    float* sWs    = sRed   + 32;     // 8 rows x 512 floats workspace

    const int tid = threadIdx.x;
    const int b0  = blockIdx.x * RR;

    // ---- stage weights (paired layouts) ----
    for (int i = tid; i < 16384; i += NTHR) {
        int e = i & 1, l = (i >> 1) & 31, g = (i >> 6) & 3, k = i >> 8;
        int col = g * 64 + 2 * l + e;
        sWih2[i] = W_ih[col * 64 + k];
        sWhh2[i] = W_hh[col * 64 + k];
    }
    for (int i = tid; i < 2048; i += NTHR) {
        int e = i & 1, l = (i >> 1) & 31, n = i >> 6;
        sWth2[i] = td_h_W[(2 * l + e) * NN + n];
    }
    for (int i = tid; i < 2048; i += NTHR) {
        int e = i & 1, n = (i >> 1) & 31, jp = i >> 6;
        sWhi2[i] = hist_W[n * HH + 2 * jp + e];
    }
    for (int i = tid; i < 1024; i += NTHR) {
        int e = i & 1, n = (i >> 1) & 31, kp = i >> 6;
        int k = 2 * kp + e;
        sWfe2[i] = (k == n) ? 0.0f : feat_W[n * NN + k];
    }
    for (int i = tid; i < 2048; i += NTHR) {
        int e = i & 1, n = (i >> 1) & 31, kp = i >> 6;
        sWwc2[i] = wc_W[n * (2 * NN) + 2 * kp + e];
    }
    if (tid < 64) { sBth[tid] = td_h_b[tid]; sOutW[tid] = out_W[tid]; }
    for (int i = tid; i < 256; i += NTHR) sBg[i] = b_ih[i] + b_hh[i];
    if (tid < 32) {
        sTdxD[tid] = td_x_W[tid * NN + tid]; sTdxB[tid] = td_x_b[tid];
        sBhist[tid] = hist_b[tid]; sBfeat[tid] = feat_b[tid]; sBwc[tid] = wc_b[tid];
    }
    __syncthreads();

    const int lane = tid & 31, w = tid >> 5;     // 4 warps
    const int rowA = 2 * w, rowB = 2 * w + 1;    // two batch rows per warp
    float* wsA = sWs + rowA * 512;
    float* wsB = sWs + rowB * 512;
    // per-row workspace: dDup u64[32] | mRow[32] | xcRow[32] | gxRow[32] |
    //                    hPair u64[32] | inpDup u64[64] | hDup u64[64]
    float* dDupA = wsA;         float* dDupB = wsB;
    float* mRowA = wsA + 64;    float* mRowB = wsB + 64;
    float* xcRowA = wsA + 96;   float* xcRowB = wsB + 96;
    float* gxRowA = wsA + 128;  float* gxRowB = wsB + 128;
    float* hPairA = wsA + 160;  float* hPairB = wsB + 160;
    float* inpDupA = wsA + 224; float* inpDupB = wsB + 224;
    float* hDupA = wsA + 352;   float* hDupB = wsB + 352;

    float hA0 = 0.f, hA1 = 0.f, cA0 = 0.f, cA1 = 0.f;
    float hB0 = 0.f, hB1 = 0.f, cB0 = 0.f, cB1 = 0.f;
    float lossAcc = 0.f;

    const size_t rowBaseA = (size_t)(b0 + rowA) * TT * NN + lane;
    const size_t rowBaseB = (size_t)(b0 + rowB) * TT * NN + lane;
    float xA = values[rowBaseA], mA = masks[rowBaseA], dA = deltas[rowBaseA];
    float xB = values[rowBaseB], mB = masks[rowBaseB], dB = deltas[rowBaseB];
    float inv_ms = gMsumInv[0];

    const u64* wthU = (const u64*)sWth2;
    const u64* whiU = (const u64*)sWhi2;
    const u64* wfeU = (const u64*)sWfe2;
    const u64* wwcU = (const u64*)sWwc2;
    const u64* wihU = (const u64*)sWih2;
    const u64* whhU = (const u64*)sWhh2;
    const u64* ddAU = (const u64*)dDupA;  const u64* ddBU = (const u64*)dDupB;
    const u64* hpAU = (const u64*)hPairA; const u64* hpBU = (const u64*)hPairB;
    const u64* xcAU = (const u64*)xcRowA; const u64* xcBU = (const u64*)xcRowB;
    const u64* gxAU = (const u64*)gxRowA; const u64* gxBU = (const u64*)gxRowB;
    const u64* mAU  = (const u64*)mRowA;  const u64* mBU  = (const u64*)mRowB;
    const u64* ipAU = (const u64*)inpDupA; const u64* ipBU = (const u64*)inpDupB;
    const u64* hdAU = (const u64*)hDupA;   const u64* hdBU = (const u64*)hDupB;

    for (int t = 0; t < TT; t++) {
        const size_t offA = rowBaseA + (size_t)t * NN;
        const size_t offB = rowBaseB + (size_t)t * NN;

        *(u64*)(dDupA + 2 * lane) = dupf(dA); mRowA[lane] = mA;
        *(u64*)(dDupB + 2 * lane) = dupf(dB); mRowB[lane] = mB;
        __syncwarp();  // W1

        // ---- gamma_h + decay, units (2l, 2l+1), both rows ----
        {
            u64 a0 = *(const u64*)(sBth + 2 * lane), a1 = 0ull;
            u64 b0v = a0, b1 = 0ull;
#pragma unroll 8
            for (int n = 0; n < 32; n += 2) {
                u64 w0 = wthU[n * 32 + lane], w1 = wthU[(n + 1) * 32 + lane];
                FMA2(a0, w0, ddAU[n], a0);   FMA2(a1, w1, ddAU[n + 1], a1);
                FMA2(b0v, w0, ddBU[n], b0v); FMA2(b1, w1, ddBU[n + 1], b1);
            }
            ADD2(a0, a0, a1); ADD2(b0v, b0v, b1);
            hA0 *= __expf(-fmaxf(lo_f(a0), 0.f));
            hA1 *= __expf(-fmaxf(hi_f(a0), 0.f));
            hB0 *= __expf(-fmaxf(lo_f(b0v), 0.f));
            hB1 *= __expf(-fmaxf(hi_f(b0v), 0.f));
            u64 hp;
            PACK2(hp, __float_as_uint(hA0), __float_as_uint(hA1));
            *(u64*)(hPairA + 2 * lane) = hp;
            PACK2(hp, __float_as_uint(hB0), __float_as_uint(hB1));
            *(u64*)(hPairB + 2 * lane) = hp;
            *(u64*)(hDupA + 4 * lane)     = dupf(hA0);
            *(u64*)(hDupA + 4 * lane + 2) = dupf(hA1);
            *(u64*)(hDupB + 4 * lane)     = dupf(hB0);
            *(u64*)(hDupB + 4 * lane + 2) = dupf(hB1);
        }
        __syncwarp();  // W2

        // ---- x_h / x_c / gamma_x for series `lane`, both rows ----
        float x_hA, e1A, x_hB, e1B;
        {
            u64 a0 = 0ull, a1 = 0ull, b0v = 0ull, b1 = 0ull;
#pragma unroll 8
            for (int jp = 0; jp < 32; jp += 2) {
                u64 w0 = whiU[jp * 32 + lane], w1 = whiU[(jp + 1) * 32 + lane];
                FMA2(a0, w0, hpAU[jp], a0);   FMA2(a1, w1, hpAU[jp + 1], a1);
                FMA2(b0v, w0, hpBU[jp], b0v); FMA2(b1, w1, hpBU[jp + 1], b1);
            }
            ADD2(a0, a0, a1); ADD2(b0v, b0v, b1);
            const float bh = sBhist[lane];
            x_hA = lo_f(a0) + hi_f(a0) + bh;
            x_hB = lo_f(b0v) + hi_f(b0v) + bh;
            xcRowA[lane] = fmaf(mA, xA - x_hA, x_hA);
            xcRowB[lane] = fmaf(mB, xB - x_hB, x_hB);
            const float td = sTdxD[lane], tb = sTdxB[lane];
            gxRowA[lane] = __expf(-fmaxf(fmaf(dA, td, tb), 0.f));
            gxRowB[lane] = __expf(-fmaxf(fmaf(dB, td, tb), 0.f));
            e1A = fabsf(xA - x_hA);
            e1B = fabsf(xB - x_hB);
        }
        __syncwarp();  // W3

        // ---- z_h, alpha, c_h, c_c, loss, imputation, both rows ----
        {
            u64 zA = 0ull, zB = 0ull;
#pragma unroll 8
            for (int kp = 0; kp < 16; kp++) {
                u64 wv = wfeU[kp * 32 + lane];
                FMA2(zA, wv, xcAU[kp], zA);
                FMA2(zB, wv, xcBU[kp], zB);
            }
            const float bf = sBfeat[lane];
            float zAv = lo_f(zA) + hi_f(zA) + bf;
            float zBv = lo_f(zB) + hi_f(zB) + bf;

            u64 aA = 0ull, aB = 0ull;
#pragma unroll 8
            for (int kp = 0; kp < 16; kp++) {
                u64 w0 = wwcU[kp * 32 + lane];
                u64 w1 = wwcU[(16 + kp) * 32 + lane];
                FMA2(aA, w0, gxAU[kp], aA); FMA2(aA, w1, mAU[kp], aA);
                FMA2(aB, w0, gxBU[kp], aB); FMA2(aB, w1, mBU[kp], aB);
            }
            const float bw = sBwc[lane];
            float alA = lo_f(aA) + hi_f(aA) + bw;
            float alB = lo_f(aB) + hi_f(aB) + bw;

            float chA = fmaf(alA, zAv - x_hA, x_hA);
            float ccA = fmaf(mA, xA - chA, chA);
            float chB = fmaf(alB, zBv - x_hB, x_hB);
            float ccB = fmaf(mB, xB - chB, chB);
            lossAcc = fmaf((e1A + fabsf(xA - zAv) + fabsf(xA - chA)) * mA, inv_ms, lossAcc);
            lossAcc = fmaf((e1B + fabsf(xB - zBv) + fabsf(xB - chB)) * mB, inv_ms, lossAcc);
            out_imp[offA] = ccA;
            out_imp[offB] = ccB;
            *(u64*)(inpDupA + 2 * lane)      = dupf(ccA);
            *(u64*)(inpDupA + 64 + 2 * lane) = dupf(mA);
            *(u64*)(inpDupB + 2 * lane)      = dupf(ccB);
            *(u64*)(inpDupB + 64 + 2 * lane) = dupf(mB);
        }
        __syncwarp();  // W4

        // ---- prefetch t+1 (LDG hides behind gates) ----
        {
            const int tn = (t + 1 < TT) ? (t + 1) : t;
            const size_t oA = rowBaseA + (size_t)tn * NN;
            const size_t oB = rowBaseB + (size_t)tn * NN;
            xA = values[oA]; mA = masks[oA]; dA = deltas[oA];
            xB = values[oB]; mB = masks[oB]; dB = deltas[oB];
            inv_ms = gMsumInv[tn];
        }

        // ---- gates + LSTM: each weight load feeds BOTH rows ----
        {
            u64 aIA = *(const u64*)(sBg + 2 * lane);
            u64 aFA = *(const u64*)(sBg + 64 + 2 * lane);
            u64 aGA = *(const u64*)(sBg + 128 + 2 * lane);
            u64 aOA = *(const u64*)(sBg + 192 + 2 * lane);
            u64 aIB = aIA, aFB = aFA, aGB = aGA, aOB = aOA;
#pragma unroll 16
            for (int k = 0; k < 64; k++) {
                u64 wI = wihU[(k * 4 + 0) * 32 + lane];
                u64 wF = wihU[(k * 4 + 1) * 32 + lane];
                u64 wG = wihU[(k * 4 + 2) * 32 + lane];
                u64 wO = wihU[(k * 4 + 3) * 32 + lane];
                u64 actA = ipAU[k], actB = ipBU[k];
                FMA2(aIA, wI, actA, aIA); FMA2(aIB, wI, actB, aIB);
                FMA2(aFA, wF, actA, aFA); FMA2(aFB, wF, actB, aFB);
                FMA2(aGA, wG, actA, aGA); FMA2(aGB, wG, actB, aGB);
                FMA2(aOA, wO, actA, aOA); FMA2(aOB, wO, actB, aOB);
            }
#pragma unroll 16
            for (int k = 0; k < 64; k++) {
                u64 wI = whhU[(k * 4 + 0) * 32 + lane];
                u64 wF = whhU[(k * 4 + 1) * 32 + lane];
                u64 wG = whhU[(k * 4 + 2) * 32 + lane];
                u64 wO = whhU[(k * 4 + 3) * 32 + lane];
                u64 actA = hdAU[k], actB = hdBU[k];
                FMA2(aIA, wI, actA, aIA); FMA2(aIB, wI, actB, aIB);
                FMA2(aFA, wF, actA, aFA); FMA2(aFB, wF, actB, aFB);
                FMA2(aGA, wG, actA, aGA); FMA2(aGB, wG, actB, aGB);
                FMA2(aOA, wO, actA, aOA); FMA2(aOB, wO, actB, aOB);
            }
            cA0 = sigmf(lo_f(aFA)) * cA0 + sigmf(lo_f(aIA)) * tanhfast(lo_f(aGA));
            hA0 = sigmf(lo_f(aOA)) * tanhfast(cA0);
            cA1 = sigmf(hi_f(aFA)) * cA1 + sigmf(hi_f(aIA)) * tanhfast(hi_f(aGA));
            hA1 = sigmf(hi_f(aOA)) * tanhfast(cA1);
            cB0 = sigmf(lo_f(aFB)) * cB0 + sigmf(lo_f(aIB)) * tanhfast(lo_f(aGB));
            hB0 = sigmf(lo_f(aOB)) * tanhfast(cB0);
            cB1 = sigmf(hi_f(aFB)) * cB1 + sigmf(hi_f(aIB)) * tanhfast(hi_f(aGB));
            hB1 = sigmf(hi_f(aOB)) * tanhfast(cB1);
        }
        // next W1 orders workspace rewrites against this iteration's readers.
    }

    // ---- output head + loss reduce (warp-local) ----
    float yA = sOutW[2 * lane] * hA0 + sOutW[2 * lane + 1] * hA1;
    float yB = sOutW[2 * lane] * hB0 + sOutW[2 * lane + 1] * hB1;
#pragma unroll
    for (int o = 16; o; o >>= 1) {
        yA += __shfl_xor_sync(0xffffffffu, yA, o);
        yB += __shfl_xor_sync(0xffffffffu, yB, o);
        lossAcc += __shfl_xor_sync(0xffffffffu, lossAcc, o);
    }

    float yLA = 0.f, tLA = 0.f, yLB = 0.f, tLB = 0.f;
    if (lane == 0) {
        float ob = out_b[0];
        float ya = yA + ob, yb = yB + ob;
        out_pred[b0 + rowA] = sigmf(ya);
        out_pred[b0 + rowB] = sigmf(yb);
        float labA = labels[b0 + rowA], itrA = is_train[b0 + rowA];
        float labB = labels[b0 + rowB], itrB = is_train[b0 + rowB];
        float mvA = fmaxf(-ya, 0.f);
        float bceA = ya - ya * labA + mvA + __logf(__expf(-mvA) + __expf(-ya - mvA));
        float mvB = fmaxf(-yb, 0.f);
        float bceB = yb - yb * labB + mvB + __logf(__expf(-mvB) + __expf(-yb - mvB));
        yLA = bceA * itrA; tLA = itrA;
        yLB = bceB * itrB; tLB = itrB;
    }
    __syncthreads();
    if (lane == 0) {
        sRed[rowA] = lossAcc; sRed[rowB] = 0.f;   // lossAcc covers both rows
        sRed[8 + rowA] = yLA; sRed[8 + rowB] = yLB;
        sRed[16 + rowA] = tLA; sRed[16 + rowB] = tLB;
    }
    __syncthreads();
    if (tid == 0) {
        float xl = 0.f, ys = 0.f, ts = 0.f;
#pragma unroll
        for (int i = 0; i < 8; i++) { xl += sRed[i]; ys += sRed[8 + i]; ts += sRed[16 + i]; }
        gXloss[blockIdx.x] = xl;
        gYsum[blockIdx.x]  = ys;
        gTsum[blockIdx.x]  = ts;
    }
}

// ---------------------------------------------------------------------------
// K3: deterministic final combine
// ---------------------------------------------------------------------------
__global__ void k_final(float* __restrict__ out) {
    float xl = 0.f, ys = 0.f, ts = 0.f;
    for (int i = 0; i < NBLK; i++) { xl += gXloss[i]; ys += gYsum[i]; ts += gTsum[i]; }
    out[0] = xl / (float)TT + 0.1f * (ys / (ts + 1e-5f));
}

extern "C" void kernel_launch(void* const* d_in, const int* in_sizes, int n_in,
                              void* d_out, int out_size) {
    const float* values   = (const float*)d_in[0];
    const float* masks    = (const float*)d_in[1];
    const float* deltas   = (const float*)d_in[2];
    // d_in[3] evals, d_in[4] eval_masks: unused by the forward outputs
    const float* labels   = (const float*)d_in[5];
    const float* is_train = (const float*)d_in[6];
    const float* td_h_W   = (const float*)d_in[7];
    const float* td_h_b   = (const float*)d_in[8];
    const float* td_x_W   = (const float*)d_in[9];
    const float* td_x_b   = (const float*)d_in[10];
    const float* hist_W   = (const float*)d_in[11];
    const float* hist_b   = (const float*)d_in[12];
    const float* feat_W   = (const float*)d_in[13];
    const float* feat_b   = (const float*)d_in[14];
    const float* wc_W     = (const float*)d_in[15];
    const float* wc_b     = (const float*)d_in[16];
    const float* W_ih     = (const float*)d_in[17];
    const float* W_hh     = (const float*)d_in[18];
    const float* b_ih     = (const float*)d_in[19];
    const float* b_hh     = (const float*)d_in[20];
    const float* out_W    = (const float*)d_in[21];
    const float* out_b    = (const float*)d_in[22];
    float* out = (float*)d_out;

    cudaFuncSetAttribute(k_main, cudaFuncAttributeMaxDynamicSharedMemorySize, SMEM_BYTES);

    // out layout: [loss(1) | predictions(B) | imputations(B*T*N)]
    k_msum<<<TT, 256>>>(masks);
    k_main<<<NBLK, NTHR, SMEM_BYTES>>>(values, masks, deltas, labels, is_train,
                                       td_h_W, td_h_b, td_x_W, td_x_b,
                                       hist_W, hist_b, feat_W, feat_b,
                                       wc_W, wc_b, W_ih, W_hh, b_ih, b_hh,
                                       out_W, out_b,
                                       out + 1, out + 1 + BB);
    k_final<<<1, 1>>>(out);
}